// round 1
// baseline (speedup 1.0000x reference)
#include <cuda_runtime.h>
#include <cuda_bf16.h>
#include <math.h>

// Problem constants
constexpr int VOCAB = 10000;
constexpr int EMB   = 1500;
constexpr int HID   = 1500;
constexpr int T     = 35;
constexpr int B     = 64;
constexpr float FORGET_BIAS = 1.0f;
constexpr int KSPLIT = 3;

// ---------------- scratch layout (single static device array) ----------------
constexpr size_t N_INPUTS = (size_t)T * B * EMB;        // 3,360,000
constexpr size_t N_XZ0    = (size_t)T * B * 4 * HID;    // 13,440,000
constexpr size_t N_OUT    = (size_t)T * B * HID;        // 3,360,000
constexpr size_t N_LOGITS = (size_t)T * B * VOCAB;      // 22,400,000
constexpr size_t N_HCAT   = (size_t)B * 2 * HID;        // 192,000
constexpr size_t N_C      = (size_t)B * HID;            // 96,000
constexpr size_t N_ZPART  = (size_t)KSPLIT * B * 4 * HID; // 1,152,000
constexpr size_t N_NLL    = (size_t)T * B;              // 2,240

constexpr size_t OFF_INPUTS = 0;
constexpr size_t OFF_XZ0    = OFF_INPUTS + N_INPUTS;
constexpr size_t OFF_OUT    = OFF_XZ0 + N_XZ0;
constexpr size_t OFF_LOGITS = OFF_OUT + N_OUT;
constexpr size_t OFF_HCAT   = OFF_LOGITS + N_LOGITS;
constexpr size_t OFF_C0     = OFF_HCAT + N_HCAT;
constexpr size_t OFF_C1     = OFF_C0 + N_C;
constexpr size_t OFF_ZPART  = OFF_C1 + N_C;
constexpr size_t OFF_NLL    = OFF_ZPART + N_ZPART;
constexpr size_t TOTAL_F    = OFF_NLL + N_NLL;

__device__ float g_scratch[TOTAL_F];

__device__ __forceinline__ float sigmoidf_(float x) {
    return 1.0f / (1.0f + expf(-x));
}

// ---------------- embedding gather ----------------
__global__ void embed_kernel(const int* __restrict__ x, const float* __restrict__ emb) {
    const int row = blockIdx.x;              // 0..T*B-1
    const int tok = x[row];
    const float4* src = reinterpret_cast<const float4*>(emb + (size_t)tok * EMB);
    float4* dst = reinterpret_cast<float4*>(g_scratch + OFF_INPUTS + (size_t)row * EMB);
    for (int i = threadIdx.x; i < EMB / 4; i += blockDim.x) dst[i] = src[i];
}

// ---------------- zero recurrent state ----------------
__global__ void zero_state_kernel() {
    const int n = (int)(N_HCAT + 2 * N_C);   // hcat, c0, c1 are contiguous
    for (int i = blockIdx.x * blockDim.x + threadIdx.x; i < n; i += gridDim.x * blockDim.x)
        g_scratch[OFF_HCAT + i] = 0.0f;
}

// ---------------- generic fp32 register-tiled GEMM (C = A @ B) ----------------
// Supports K-splitting across gridDim.z: block z handles K range
// [z*kchunk, min(K,(z+1)*kchunk)) and writes to C + z*partStride.
template<int BM, int BN, int BK, int TM, int TN>
__global__ void gemm_nn(const float* __restrict__ A, const float* __restrict__ Bm,
                        float* __restrict__ C,
                        int M, int N, int K,
                        int lda, int ldb, int ldc,
                        int kchunk, long long partStride)
{
    constexpr int TX = BN / TN;
    constexpr int TY = BM / TM;
    constexpr int THREADS = TX * TY;
    __shared__ float As[BK][BM + 4];
    __shared__ float Bs[BK][BN + 4];

    const int tid = threadIdx.x;
    const int tx = tid % TX;
    const int ty = tid / TX;
    const int row0 = blockIdx.y * BM;
    const int col0 = blockIdx.x * BN;
    const int kstart = blockIdx.z * kchunk;
    const int kend = min(K, kstart + kchunk);
    C += (long long)blockIdx.z * partStride;

    float acc[TM][TN];
#pragma unroll
    for (int i = 0; i < TM; i++)
#pragma unroll
        for (int j = 0; j < TN; j++) acc[i][j] = 0.0f;

    for (int k0 = kstart; k0 < kend; k0 += BK) {
        // A tile (BM x BK) -> transposed As[k][m]
        {
            const int ak = tid % BK;
            const int gk = k0 + ak;
            const bool kok = gk < kend;
#pragma unroll
            for (int r = tid / BK; r < BM; r += THREADS / BK) {
                const int gr = row0 + r;
                float v = 0.0f;
                if (kok && gr < M) v = A[(long long)gr * lda + gk];
                As[ak][r] = v;
            }
        }
        // B tile (BK x BN)
        {
            const int bc = tid % BN;
            const int gc = col0 + bc;
            const bool cok = gc < N;
#pragma unroll
            for (int r = tid / BN; r < BK; r += THREADS / BN) {
                const int gk = k0 + r;
                float v = 0.0f;
                if (cok && gk < kend) v = Bm[(long long)gk * ldb + gc];
                Bs[r][bc] = v;
            }
        }
        __syncthreads();
#pragma unroll
        for (int k = 0; k < BK; k++) {
            float af[TM], bf[TN];
#pragma unroll
            for (int i = 0; i < TM; i++) af[i] = As[k][ty * TM + i];
#pragma unroll
            for (int j = 0; j < TN; j++) bf[j] = Bs[k][tx * TN + j];
#pragma unroll
            for (int i = 0; i < TM; i++)
#pragma unroll
                for (int j = 0; j < TN; j++) acc[i][j] += af[i] * bf[j];
        }
        __syncthreads();
    }

#pragma unroll
    for (int i = 0; i < TM; i++) {
        const int r = row0 + ty * TM + i;
        if (r >= M) continue;
#pragma unroll
        for (int j = 0; j < TN; j++) {
            const int c = col0 + tx * TN + j;
            if (c < N) C[(long long)r * ldc + c] = acc[i][j];
        }
    }
}

// ---------------- LSTM gate kernels ----------------
// Layer 0: z = xz0[t] (precomputed x-part) + sum_p zpart[p] (h-part) + b0
__global__ void gates0_kernel(const float* __restrict__ b0, int t) {
    const int idx = blockIdx.x * blockDim.x + threadIdx.x;
    if (idx >= B * HID) return;
    const int bb = idx / HID, j = idx % HID;
    const float* xz = g_scratch + OFF_XZ0 + (size_t)(t * B + bb) * (4 * HID);
    float zi = xz[j]           + b0[j];
    float zj = xz[j + HID]     + b0[j + HID];
    float zf = xz[j + 2 * HID] + b0[j + 2 * HID];
    float zo = xz[j + 3 * HID] + b0[j + 3 * HID];
#pragma unroll
    for (int p = 0; p < KSPLIT; p++) {
        const float* z = g_scratch + OFF_ZPART + (size_t)p * (B * 4 * HID) + (size_t)bb * (4 * HID);
        zi += z[j]; zj += z[j + HID]; zf += z[j + 2 * HID]; zo += z[j + 3 * HID];
    }
    float c = g_scratch[OFF_C0 + idx];
    float cn = c * sigmoidf_(zf + FORGET_BIAS) + sigmoidf_(zi) * tanhf(zj);
    g_scratch[OFF_C0 + idx] = cn;
    g_scratch[OFF_HCAT + (size_t)bb * (2 * HID) + j] = tanhf(cn) * sigmoidf_(zo);
}

// Layer 1: z = sum_p zpart[p] + b1 ; writes h1 into hcat right half + outputs[t]
__global__ void gates1_kernel(const float* __restrict__ b1, int t) {
    const int idx = blockIdx.x * blockDim.x + threadIdx.x;
    if (idx >= B * HID) return;
    const int bb = idx / HID, j = idx % HID;
    float zi = b1[j];
    float zj = b1[j + HID];
    float zf = b1[j + 2 * HID];
    float zo = b1[j + 3 * HID];
#pragma unroll
    for (int p = 0; p < KSPLIT; p++) {
        const float* z = g_scratch + OFF_ZPART + (size_t)p * (B * 4 * HID) + (size_t)bb * (4 * HID);
        zi += z[j]; zj += z[j + HID]; zf += z[j + 2 * HID]; zo += z[j + 3 * HID];
    }
    float c = g_scratch[OFF_C1 + idx];
    float cn = c * sigmoidf_(zf + FORGET_BIAS) + sigmoidf_(zi) * tanhf(zj);
    g_scratch[OFF_C1 + idx] = cn;
    const float h = tanhf(cn) * sigmoidf_(zo);
    g_scratch[OFF_HCAT + (size_t)bb * (2 * HID) + HID + j] = h;
    g_scratch[OFF_OUT + (size_t)(t * B + bb) * HID + j] = h;
}

// ---------------- log-softmax + NLL per row ----------------
__global__ void row_nll_kernel(const float* __restrict__ sb, const int* __restrict__ y) {
    __shared__ float red[256];
    const int row = blockIdx.x;
    const float* lr = g_scratch + OFF_LOGITS + (size_t)row * VOCAB;
    float m = -1e30f;
    for (int v = threadIdx.x; v < VOCAB; v += 256) m = fmaxf(m, lr[v] + sb[v]);
    red[threadIdx.x] = m; __syncthreads();
    for (int s = 128; s > 0; s >>= 1) {
        if (threadIdx.x < s) red[threadIdx.x] = fmaxf(red[threadIdx.x], red[threadIdx.x + s]);
        __syncthreads();
    }
    m = red[0]; __syncthreads();
    float sum = 0.0f;
    for (int v = threadIdx.x; v < VOCAB; v += 256) sum += expf(lr[v] + sb[v] - m);
    red[threadIdx.x] = sum; __syncthreads();
    for (int s = 128; s > 0; s >>= 1) {
        if (threadIdx.x < s) red[threadIdx.x] += red[threadIdx.x + s];
        __syncthreads();
    }
    if (threadIdx.x == 0) {
        const int tgt = y[row];
        g_scratch[OFF_NLL + row] = m + logf(red[0]) - (lr[tgt] + sb[tgt]);
    }
}

__global__ void final_loss_kernel(float* __restrict__ out) {
    __shared__ float red[256];
    float s = 0.0f;
    for (int i = threadIdx.x; i < T * B; i += 256) s += g_scratch[OFF_NLL + i];
    red[threadIdx.x] = s; __syncthreads();
    for (int st = 128; st > 0; st >>= 1) {
        if (threadIdx.x < st) red[threadIdx.x] += red[threadIdx.x + st];
        __syncthreads();
    }
    if (threadIdx.x == 0) out[0] = red[0] / (float)B;
}

// ---------------- launch ----------------
extern "C" void kernel_launch(void* const* d_in, const int* in_sizes, int n_in,
                              void* d_out, int out_size) {
    const int*   x   = (const int*)d_in[0];
    const int*   y   = (const int*)d_in[1];
    const float* emb = (const float*)d_in[2];
    const float* W0  = (const float*)d_in[3];
    const float* b0  = (const float*)d_in[4];
    const float* W1  = (const float*)d_in[5];
    const float* b1  = (const float*)d_in[6];
    const float* sw  = (const float*)d_in[7];
    const float* sb  = (const float*)d_in[8];
    float* out = (float*)d_out;

    void* basev = nullptr;
    cudaGetSymbolAddress(&basev, g_scratch);
    float* base = (float*)basev;

    float* sInputs = base + OFF_INPUTS;
    float* sXz0    = base + OFF_XZ0;
    float* sOut    = base + OFF_OUT;
    float* sLogits = base + OFF_LOGITS;
    float* sHcat   = base + OFF_HCAT;
    float* sZpart  = base + OFF_ZPART;

    // 1) state zero + embedding gather
    zero_state_kernel<<<256, 256>>>();
    embed_kernel<<<T * B, 128>>>(x, emb);

    // 2) precompute x-part of layer0 for all timesteps: xz0 = inputs @ W0[0:EMB,:]
    {
        dim3 grid((6000 + 127) / 128, (T * B + 127) / 128, 1);
        gemm_nn<128, 128, 16, 8, 8><<<grid, 256>>>(
            sInputs, W0, sXz0, T * B, 4 * HID, EMB,
            EMB, 4 * HID, 4 * HID, EMB, 0);
    }

    // 3) sequential recurrence
    const int gatesBlocks = (B * HID + 255) / 256;
    for (int t = 0; t < T; t++) {
        // layer0 h-part: zpart = h0 @ W0h   (A = hcat[:, :HID], lda=2*HID)
        {
            dim3 grid((6000 + 127) / 128, 1, KSPLIT);
            gemm_nn<64, 128, 16, 8, 8><<<grid, 128>>>(
                sHcat, W0 + (size_t)EMB * (4 * HID), sZpart,
                B, 4 * HID, HID,
                2 * HID, 4 * HID, 4 * HID,
                HID / KSPLIT, (long long)B * 4 * HID);
        }
        gates0_kernel<<<gatesBlocks, 256>>>(b0, t);
        // layer1: zpart = [h0, h1_prev] @ W1
        {
            dim3 grid((6000 + 127) / 128, 1, KSPLIT);
            gemm_nn<64, 128, 16, 8, 8><<<grid, 128>>>(
                sHcat, W1, sZpart,
                B, 4 * HID, 2 * HID,
                2 * HID, 4 * HID, 4 * HID,
                (2 * HID) / KSPLIT, (long long)B * 4 * HID);
        }
        gates1_kernel<<<gatesBlocks, 256>>>(b1, t);
    }

    // 4) logits = outputs @ softmax_w
    {
        dim3 grid((VOCAB + 127) / 128, (T * B + 127) / 128, 1);
        gemm_nn<128, 128, 16, 8, 8><<<grid, 256>>>(
            sOut, sw, sLogits, T * B, VOCAB, HID,
            HID, VOCAB, VOCAB, HID, 0);
    }

    // 5) per-row log-softmax NLL, then deterministic final reduction
    row_nll_kernel<<<T * B, 256>>>(sb, y);
    final_loss_kernel<<<1, 256>>>(out);
}

// round 2
// speedup vs baseline: 11.9157x; 11.9157x over previous
#include <cuda_runtime.h>
#include <cuda_bf16.h>
#include <math.h>
#include <stdint.h>

// Problem constants
constexpr int VOCAB = 10000;
constexpr int EMB   = 1500;
constexpr int HID   = 1500;
constexpr int T     = 35;
constexpr int B     = 64;
constexpr float FORGET_BIAS = 1.0f;
constexpr int KSPLIT = 3;

// ---------------- static device scratch ----------------
__device__ __align__(128) float g_xz0[(size_t)T * B * 4 * HID];      // 13.44M
__device__ __align__(128) float g_logits[(size_t)T * B * VOCAB];     // 22.4M
__device__ __align__(128) float g_zpart[(size_t)KSPLIT * B * 4 * HID];
__device__ __align__(128) float g_c0[B * HID];
__device__ __align__(128) float g_c1[B * HID];
__device__ __align__(128) float g_nll[T * B];
__device__ __align__(128) __nv_bfloat16 g_inputs[(size_t)T * B * EMB];
__device__ __align__(128) __nv_bfloat16 g_W0b[(size_t)(EMB + HID) * 4 * HID];
__device__ __align__(128) __nv_bfloat16 g_W1b[(size_t)2 * HID * 4 * HID];
__device__ __align__(128) __nv_bfloat16 g_swb[(size_t)HID * VOCAB];
__device__ __align__(128) __nv_bfloat16 g_hcat[B * 2 * HID];
__device__ __align__(128) __nv_bfloat16 g_out[(size_t)T * B * HID];

__device__ __forceinline__ float sigmoidf_(float x) {
    return 1.0f / (1.0f + expf(-x));
}

// ---------------- fp32 -> bf16 conversion (vectorized, n must be even) ----------------
__global__ void f2bf_kernel(const float* __restrict__ src, __nv_bfloat16* __restrict__ dst, int n2) {
    const float2* s2 = reinterpret_cast<const float2*>(src);
    __nv_bfloat162* d2 = reinterpret_cast<__nv_bfloat162*>(dst);
    int i = blockIdx.x * blockDim.x + threadIdx.x;
    const int stride = gridDim.x * blockDim.x;
    for (; i < n2; i += stride) {
        float2 v = s2[i];
        d2[i] = __floats2bfloat162_rn(v.x, v.y);
    }
}

// ---------------- embedding gather (fp32 table -> bf16 rows) ----------------
__global__ void embed_kernel(const int* __restrict__ x, const float* __restrict__ emb) {
    const int row = blockIdx.x;                       // 0..T*B-1
    const int tok = x[row];
    const float2* src = reinterpret_cast<const float2*>(emb + (size_t)tok * EMB);
    __nv_bfloat162* dst = reinterpret_cast<__nv_bfloat162*>(g_inputs + (size_t)row * EMB);
    for (int i = threadIdx.x; i < EMB / 2; i += blockDim.x) {
        float2 v = src[i];
        dst[i] = __floats2bfloat162_rn(v.x, v.y);
    }
}

// ---------------- zero recurrent state ----------------
__global__ void zero_state_kernel() {
    const int i = blockIdx.x * blockDim.x + threadIdx.x;
    if (i < B * HID) { g_c0[i] = 0.0f; g_c1[i] = 0.0f; }
    if (i < B * 2 * HID) g_hcat[i] = __float2bfloat16(0.0f);
}

// ---------------- bf16 tensor-core GEMM: C(f32) = A(bf16,row) @ B(bf16,row) ----------------
// K-split across gridDim.z: block z covers K range [z*kchunk, min(K,(z+1)*kchunk)),
// writing its partial to C + z*partStride.
template<int BM, int BN, int BK, int WARPS_M, int WARPS_N>
__global__ void __launch_bounds__(WARPS_M * WARPS_N * 32)
gemm_bf16(const __nv_bfloat16* __restrict__ A, const __nv_bfloat16* __restrict__ Bm,
          float* __restrict__ C, int M, int N, int K,
          int lda, int ldb, int ldc, int kchunk, long long partStride)
{
    constexpr int THREADS = WARPS_M * WARPS_N * 32;
    constexpr int WM = BM / WARPS_M;
    constexpr int WN = BN / WARPS_N;
    constexpr int MT = WM / 16;   // m16 tiles per warp
    constexpr int NT = WN / 8;    // n8 tiles per warp
    constexpr int NT2 = WN / 16;  // n16 ldmatrix groups per warp

    __shared__ __align__(16) __nv_bfloat16 As[BM][BK + 8];
    __shared__ __align__(16) __nv_bfloat16 Bs[BK][BN + 8];

    const int tid = threadIdx.x;
    const int lane = tid & 31;
    const int warp = tid >> 5;
    const int wm = warp / WARPS_N;
    const int wn = warp % WARPS_N;
    const int row0 = blockIdx.y * BM;
    const int col0 = blockIdx.x * BN;
    const int kstart = blockIdx.z * kchunk;
    const int kend = min(K, kstart + kchunk);
    C += (long long)blockIdx.z * partStride;

    float acc[MT][NT][4];
#pragma unroll
    for (int mt = 0; mt < MT; mt++)
#pragma unroll
        for (int nt = 0; nt < NT; nt++)
#pragma unroll
            for (int r = 0; r < 4; r++) acc[mt][nt][r] = 0.0f;

    // ldmatrix per-lane addressing: matrix = lane/8, row-in-matrix = lane%8
    const int lrow = ((lane >> 3) & 1) * 8 + (lane & 7);
    const int lcol = (lane >> 4) * 8;

    for (int k0 = kstart; k0 < kend; k0 += BK) {
        // ---- A tile (BM x BK), 2-bf16 (4B) vectors ----
        constexpr int A_IT = BM * BK / (2 * THREADS);
#pragma unroll
        for (int i = 0; i < A_IT; i++) {
            const int idx = tid + i * THREADS;
            const int r = idx / (BK / 2);
            const int cg = idx % (BK / 2);
            const int gr = row0 + r;
            const int gk = k0 + cg * 2;
            uint32_t v = 0u;
            if (gr < M && gk < kend)
                v = *reinterpret_cast<const uint32_t*>(A + (size_t)gr * lda + gk);
            *reinterpret_cast<uint32_t*>(&As[r][cg * 2]) = v;
        }
        // ---- B tile (BK x BN), 8-bf16 (16B) vectors; N % 8 == 0 assumed ----
        constexpr int B_IT = BK * BN / (8 * THREADS);
#pragma unroll
        for (int i = 0; i < B_IT; i++) {
            const int idx = tid + i * THREADS;
            const int r = idx / (BN / 8);
            const int g = idx % (BN / 8);
            const int gk = k0 + r;
            const int gc = col0 + g * 8;
            uint4 v = make_uint4(0u, 0u, 0u, 0u);
            if (gk < kend && gc < N)
                v = *reinterpret_cast<const uint4*>(Bm + (size_t)gk * ldb + gc);
            *reinterpret_cast<uint4*>(&Bs[r][g * 8]) = v;
        }
        __syncthreads();

#pragma unroll
        for (int ks = 0; ks < BK; ks += 16) {
            uint32_t ar[MT][4];
            uint32_t br[NT2][4];
#pragma unroll
            for (int mt = 0; mt < MT; mt++) {
                uint32_t addr = (uint32_t)__cvta_generic_to_shared(
                    &As[wm * WM + mt * 16 + lrow][ks + lcol]);
                asm volatile("ldmatrix.sync.aligned.m8n8.x4.shared.b16 {%0,%1,%2,%3}, [%4];"
                    : "=r"(ar[mt][0]), "=r"(ar[mt][1]), "=r"(ar[mt][2]), "=r"(ar[mt][3])
                    : "r"(addr));
            }
#pragma unroll
            for (int q = 0; q < NT2; q++) {
                uint32_t addr = (uint32_t)__cvta_generic_to_shared(
                    &Bs[ks + lrow][wn * WN + q * 16 + lcol]);
                asm volatile("ldmatrix.sync.aligned.m8n8.x4.trans.shared.b16 {%0,%1,%2,%3}, [%4];"
                    : "=r"(br[q][0]), "=r"(br[q][1]), "=r"(br[q][2]), "=r"(br[q][3])
                    : "r"(addr));
            }
#pragma unroll
            for (int mt = 0; mt < MT; mt++)
#pragma unroll
                for (int nt = 0; nt < NT; nt++) {
                    const int q = nt >> 1;
                    const int p = (nt & 1) * 2;
                    asm volatile(
                        "mma.sync.aligned.m16n8k16.row.col.f32.bf16.bf16.f32 "
                        "{%0,%1,%2,%3}, {%4,%5,%6,%7}, {%8,%9}, {%0,%1,%2,%3};"
                        : "+f"(acc[mt][nt][0]), "+f"(acc[mt][nt][1]),
                          "+f"(acc[mt][nt][2]), "+f"(acc[mt][nt][3])
                        : "r"(ar[mt][0]), "r"(ar[mt][1]), "r"(ar[mt][2]), "r"(ar[mt][3]),
                          "r"(br[q][p]), "r"(br[q][p + 1]));
                }
        }
        __syncthreads();
    }

    // ---- epilogue ----
#pragma unroll
    for (int mt = 0; mt < MT; mt++) {
        const int r0 = row0 + wm * WM + mt * 16 + (lane >> 2);
#pragma unroll
        for (int nt = 0; nt < NT; nt++) {
            const int c = col0 + wn * WN + nt * 8 + (lane & 3) * 2;
            if (c < N) {
                if (r0 < M) {
                    C[(long long)r0 * ldc + c]     = acc[mt][nt][0];
                    C[(long long)r0 * ldc + c + 1] = acc[mt][nt][1];
                }
                if (r0 + 8 < M) {
                    C[(long long)(r0 + 8) * ldc + c]     = acc[mt][nt][2];
                    C[(long long)(r0 + 8) * ldc + c + 1] = acc[mt][nt][3];
                }
            }
        }
    }
}

// ---------------- LSTM gate kernels ----------------
// Layer 0: z = xz0[t] (precomputed x-part) + sum_p zpart[p] (h-part) + b0
__global__ void gates0_kernel(const float* __restrict__ b0, int t) {
    const int idx = blockIdx.x * blockDim.x + threadIdx.x;
    if (idx >= B * HID) return;
    const int bb = idx / HID, j = idx % HID;
    const float* xz = g_xz0 + (size_t)(t * B + bb) * (4 * HID);
    float zi = xz[j]           + b0[j];
    float zj = xz[j + HID]     + b0[j + HID];
    float zf = xz[j + 2 * HID] + b0[j + 2 * HID];
    float zo = xz[j + 3 * HID] + b0[j + 3 * HID];
#pragma unroll
    for (int p = 0; p < KSPLIT; p++) {
        const float* z = g_zpart + (size_t)p * (B * 4 * HID) + (size_t)bb * (4 * HID);
        zi += z[j]; zj += z[j + HID]; zf += z[j + 2 * HID]; zo += z[j + 3 * HID];
    }
    float c = g_c0[idx];
    float cn = c * sigmoidf_(zf + FORGET_BIAS) + sigmoidf_(zi) * tanhf(zj);
    g_c0[idx] = cn;
    g_hcat[(size_t)bb * (2 * HID) + j] = __float2bfloat16(tanhf(cn) * sigmoidf_(zo));
}

// Layer 1: z = sum_p zpart[p] + b1 ; writes h1 into hcat right half + outputs[t]
__global__ void gates1_kernel(const float* __restrict__ b1, int t) {
    const int idx = blockIdx.x * blockDim.x + threadIdx.x;
    if (idx >= B * HID) return;
    const int bb = idx / HID, j = idx % HID;
    float zi = b1[j];
    float zj = b1[j + HID];
    float zf = b1[j + 2 * HID];
    float zo = b1[j + 3 * HID];
#pragma unroll
    for (int p = 0; p < KSPLIT; p++) {
        const float* z = g_zpart + (size_t)p * (B * 4 * HID) + (size_t)bb * (4 * HID);
        zi += z[j]; zj += z[j + HID]; zf += z[j + 2 * HID]; zo += z[j + 3 * HID];
    }
    float c = g_c1[idx];
    float cn = c * sigmoidf_(zf + FORGET_BIAS) + sigmoidf_(zi) * tanhf(zj);
    g_c1[idx] = cn;
    const float h = tanhf(cn) * sigmoidf_(zo);
    const __nv_bfloat16 hb = __float2bfloat16(h);
    g_hcat[(size_t)bb * (2 * HID) + HID + j] = hb;
    g_out[(size_t)(t * B + bb) * HID + j] = hb;
}

// ---------------- log-softmax + NLL per row ----------------
__global__ void row_nll_kernel(const float* __restrict__ sb, const int* __restrict__ y) {
    __shared__ float red[256];
    const int row = blockIdx.x;
    const float* lr = g_logits + (size_t)row * VOCAB;
    float m = -1e30f;
    for (int v = threadIdx.x; v < VOCAB; v += 256) m = fmaxf(m, lr[v] + sb[v]);
    red[threadIdx.x] = m; __syncthreads();
    for (int s = 128; s > 0; s >>= 1) {
        if (threadIdx.x < s) red[threadIdx.x] = fmaxf(red[threadIdx.x], red[threadIdx.x + s]);
        __syncthreads();
    }
    m = red[0]; __syncthreads();
    float sum = 0.0f;
    for (int v = threadIdx.x; v < VOCAB; v += 256) sum += expf(lr[v] + sb[v] - m);
    red[threadIdx.x] = sum; __syncthreads();
    for (int s = 128; s > 0; s >>= 1) {
        if (threadIdx.x < s) red[threadIdx.x] += red[threadIdx.x + s];
        __syncthreads();
    }
    if (threadIdx.x == 0) {
        const int tgt = y[row];
        g_nll[row] = m + logf(red[0]) - (lr[tgt] + sb[tgt]);
    }
}

__global__ void final_loss_kernel(float* __restrict__ out) {
    __shared__ float red[256];
    float s = 0.0f;
    for (int i = threadIdx.x; i < T * B; i += 256) s += g_nll[i];
    red[threadIdx.x] = s; __syncthreads();
    for (int st = 128; st > 0; st >>= 1) {
        if (threadIdx.x < st) red[threadIdx.x] += red[threadIdx.x + st];
        __syncthreads();
    }
    if (threadIdx.x == 0) out[0] = red[0] / (float)B;
}

// ---------------- launch ----------------
extern "C" void kernel_launch(void* const* d_in, const int* in_sizes, int n_in,
                              void* d_out, int out_size) {
    const int*   x   = (const int*)d_in[0];
    const int*   y   = (const int*)d_in[1];
    const float* emb = (const float*)d_in[2];
    const float* W0  = (const float*)d_in[3];
    const float* b0  = (const float*)d_in[4];
    const float* W1  = (const float*)d_in[5];
    const float* b1  = (const float*)d_in[6];
    const float* sw  = (const float*)d_in[7];
    const float* sb  = (const float*)d_in[8];
    float* out = (float*)d_out;

    // symbol addresses for GEMM pointer params
    void *pW0b, *pW1b, *pSwb, *pInputs, *pHcat, *pOutB, *pXz0, *pLogits, *pZpart;
    cudaGetSymbolAddress(&pW0b, g_W0b);
    cudaGetSymbolAddress(&pW1b, g_W1b);
    cudaGetSymbolAddress(&pSwb, g_swb);
    cudaGetSymbolAddress(&pInputs, g_inputs);
    cudaGetSymbolAddress(&pHcat, g_hcat);
    cudaGetSymbolAddress(&pOutB, g_out);
    cudaGetSymbolAddress(&pXz0, g_xz0);
    cudaGetSymbolAddress(&pLogits, g_logits);
    cudaGetSymbolAddress(&pZpart, g_zpart);

    // 1) weight conversion + state zero + embedding gather
    f2bf_kernel<<<2048, 256>>>(W0, (__nv_bfloat16*)pW0b, (EMB + HID) * 4 * HID / 2);
    f2bf_kernel<<<2048, 256>>>(W1, (__nv_bfloat16*)pW1b, 2 * HID * 4 * HID / 2);
    f2bf_kernel<<<2048, 256>>>(sw, (__nv_bfloat16*)pSwb, HID * VOCAB / 2);
    zero_state_kernel<<<(B * 2 * HID + 255) / 256, 256>>>();
    embed_kernel<<<T * B, 128>>>(x, emb);

    // 2) prefix: xz0 = inputs @ W0[0:EMB,:]  (M=2240, N=6000, K=1500)
    {
        dim3 grid((4 * HID + 127) / 128, (T * B + 127) / 128, 1);
        gemm_bf16<128, 128, 32, 2, 4><<<grid, 256>>>(
            (const __nv_bfloat16*)pInputs, (const __nv_bfloat16*)pW0b, (float*)pXz0,
            T * B, 4 * HID, EMB, EMB, 4 * HID, 4 * HID, EMB, 0);
    }

    // 3) sequential recurrence
    const int gatesBlocks = (B * HID + 255) / 256;
    for (int t = 0; t < T; t++) {
        // layer0 h-part: zpart = h0 @ W0h  (A = hcat[:, :HID], lda = 2*HID)
        {
            dim3 grid((4 * HID + 127) / 128, 1, KSPLIT);
            gemm_bf16<64, 128, 32, 2, 2><<<grid, 128>>>(
                (const __nv_bfloat16*)pHcat,
                (const __nv_bfloat16*)pW0b + (size_t)EMB * (4 * HID),
                (float*)pZpart,
                B, 4 * HID, HID, 2 * HID, 4 * HID, 4 * HID,
                HID / KSPLIT, (long long)B * 4 * HID);
        }
        gates0_kernel<<<gatesBlocks, 256>>>(b0, t);
        // layer1: zpart = [h0, h1_prev] @ W1  (K = 2*HID)
        {
            dim3 grid((4 * HID + 127) / 128, 1, KSPLIT);
            gemm_bf16<64, 128, 32, 2, 2><<<grid, 128>>>(
                (const __nv_bfloat16*)pHcat, (const __nv_bfloat16*)pW1b, (float*)pZpart,
                B, 4 * HID, 2 * HID, 2 * HID, 4 * HID, 4 * HID,
                (2 * HID) / KSPLIT, (long long)B * 4 * HID);
        }
        gates1_kernel<<<gatesBlocks, 256>>>(b1, t);
    }

    // 4) logits = outputs @ softmax_w  (M=2240, N=10000, K=1500)
    {
        dim3 grid((VOCAB + 127) / 128, (T * B + 127) / 128, 1);
        gemm_bf16<128, 128, 32, 2, 4><<<grid, 256>>>(
            (const __nv_bfloat16*)pOutB, (const __nv_bfloat16*)pSwb, (float*)pLogits,
            T * B, VOCAB, HID, HID, VOCAB, VOCAB, HID, 0);
    }

    // 5) per-row log-softmax NLL, then deterministic final reduction
    row_nll_kernel<<<T * B, 256>>>(sb, y);
    final_loss_kernel<<<1, 256>>>(out);
}